// round 3
// baseline (speedup 1.0000x reference)
#include <cuda_runtime.h>

// DSQN forward: B=512, T=1024, F=128, H=128, A=16. Faithful fp32.
//
// Numerics contract (must match JAX reference expression tree, fp32):
//   cur1 = (sequential-f FMA dot of x,W1row starting at 0)  THEN  + b1
//   mem  = ((clip(beta)*mem) + cur) - reset        <- three separate roundings,
//                                                     NO fma contraction here
//   cur2 = (ascending-h1 sum of W2 cols == dense seq FMA with 0/1 spk) THEN + b2
//   out  = (ascending-h  sum of W3 cols) THEN + b3
//
// Structure: 128 blocks x 128 threads, 4 batch elements per block.
//   L1: thread h holds W1[h,:] in 128 regs; x tile broadcast from double-
//       buffered smem. LIF1 -> ballot masks (double-buffered smem).
//   L2: warp w owns batch element w; sparse gather of W2^T columns (smem).
//   LIF2 + L3: ballots stay warp-uniform in registers; lanes 0..15 write out.
// Exactly one __syncthreads per timestep.

#define T_STEPS 1024
#define F_DIM   128
#define H_DIM   128
#define A_DIM   16
#define BPB     4
#define NTHREADS 128
#define NBLOCKS  128

#define SM_W2T   0
#define SM_W3T   (16384)
#define SM_XS    (16384 + 2048)
#define SM_MASKS (16384 + 2048 + 1024)
#define SM_FLOATS (16384 + 2048 + 1024 + 32)
#define SM_BYTES  (SM_FLOATS * 4)

__global__ __launch_bounds__(NTHREADS, 1)
void dsqn_kernel(const float* __restrict__ state,   // [B,T,F]
                 const float* __restrict__ hidden,  // [B,1,2,H]
                 const float* __restrict__ W1,      // [H,F]
                 const float* __restrict__ b1,      // [H]
                 const float* __restrict__ beta1,   // [H]
                 const float* __restrict__ W2,      // [H,H]
                 const float* __restrict__ b2,      // [H]
                 const float* __restrict__ beta2,   // [H]
                 const float* __restrict__ W3,      // [A,H]
                 const float* __restrict__ b3,      // [A]
                 float* __restrict__ out)           // [B,T,A]
{
    extern __shared__ float sm[];
    float* W2Ts = sm + SM_W2T;
    float* W3Ts = sm + SM_W3T;
    float* xs   = sm + SM_XS;
    unsigned* masks = reinterpret_cast<unsigned*>(sm + SM_MASKS);

    const int tid   = threadIdx.x;
    const int h     = tid;
    const int lane  = tid & 31;
    const int wid   = tid >> 5;
    const int bBase = blockIdx.x * BPB;

    // ---- W1 row h into registers ----
    float w1r[F_DIM];
    #pragma unroll
    for (int f4 = 0; f4 < 32; ++f4) {
        float4 v = *reinterpret_cast<const float4*>(&W1[h * F_DIM + f4 * 4]);
        w1r[4*f4+0] = v.x; w1r[4*f4+1] = v.y;
        w1r[4*f4+2] = v.z; w1r[4*f4+3] = v.w;
    }

    // ---- per-thread parameters ----
    const float beta1c = fminf(fmaxf(beta1[h], 0.0f), 1.0f);
    const float b1h    = b1[h];
    float beta2k[4], b2k[4];
    #pragma unroll
    for (int k = 0; k < 4; ++k) {
        int hh = lane + 32 * k;
        beta2k[k] = fminf(fmaxf(beta2[hh], 0.0f), 1.0f);
        b2k[k]    = b2[hh];
    }
    const int  al  = lane & 15;
    const float b3a = b3[al];

    // ---- membrane state ----
    float mem1[BPB];
    #pragma unroll
    for (int i = 0; i < BPB; ++i)
        mem1[i] = hidden[(size_t)(bBase + i) * 2 * H_DIM + h];
    float mem2k[4];
    #pragma unroll
    for (int k = 0; k < 4; ++k)
        mem2k[k] = hidden[(size_t)(bBase + wid) * 2 * H_DIM + H_DIM + lane + 32 * k];

    // ---- W2 transpose into smem ----
    #pragma unroll 4
    for (int q = 0; q < 32; ++q) {
        float4 v = *reinterpret_cast<const float4*>(&W2[h * H_DIM + q * 4]);
        W2Ts[(q*4+0) * H_DIM + h] = v.x;
        W2Ts[(q*4+1) * H_DIM + h] = v.y;
        W2Ts[(q*4+2) * H_DIM + h] = v.z;
        W2Ts[(q*4+3) * H_DIM + h] = v.w;
    }
    // ---- W3 transpose into smem ----
    for (int i = tid; i < A_DIM * H_DIM; i += NTHREADS) {
        int a  = i >> 7;
        int hh = i & 127;
        W3Ts[hh * A_DIM + a] = W3[i];
    }

    // ---- preload x(t=0) ----
    const int bi_p = tid >> 5;
    const int f0_p = (tid & 31) * 4;
    {
        float4 v = *reinterpret_cast<const float4*>(
            &state[((size_t)(bBase + bi_p) * T_STEPS + 0) * F_DIM + f0_p]);
        *reinterpret_cast<float4*>(&xs[(0 * BPB + bi_p) * F_DIM + f0_p]) = v;
    }
    __syncthreads();

    // ================= main temporal loop =================
    for (int t = 0; t < T_STEPS; ++t) {
        const int cb = t & 1;
        const int nb = cb ^ 1;

        // prefetch x(t+1)
        float4 xn = make_float4(0.f, 0.f, 0.f, 0.f);
        if (t + 1 < T_STEPS)
            xn = *reinterpret_cast<const float4*>(
                &state[((size_t)(bBase + bi_p) * T_STEPS + (t + 1)) * F_DIM + f0_p]);

        // ---- layer 1: sequential-f FMA dot, bias added AFTER ----
        float acc[BPB] = {0.f, 0.f, 0.f, 0.f};
        const float* xbase = &xs[cb * BPB * F_DIM];
        #pragma unroll
        for (int f4 = 0; f4 < 32; ++f4) {
            #pragma unroll
            for (int i = 0; i < BPB; ++i) {
                float4 v = *reinterpret_cast<const float4*>(&xbase[i * F_DIM + f4 * 4]);
                acc[i] = fmaf(v.x, w1r[4*f4+0], acc[i]);
                acc[i] = fmaf(v.y, w1r[4*f4+1], acc[i]);
                acc[i] = fmaf(v.z, w1r[4*f4+2], acc[i]);
                acc[i] = fmaf(v.w, w1r[4*f4+3], acc[i]);
            }
        }

        // ---- LIF1: unfused ((beta*mem) + cur) - reset ----
        #pragma unroll
        for (int i = 0; i < BPB; ++i) {
            float cur   = __fadd_rn(acc[i], b1h);             // dot THEN + b1
            float reset = (mem1[i] > 1.0f) ? 1.0f : 0.0f;
            float bm    = __fmul_rn(beta1c, mem1[i]);         // separate mul
            float m     = __fsub_rn(__fadd_rn(bm, cur), reset); // separate adds
            mem1[i] = m;
            unsigned msk = __ballot_sync(0xFFFFFFFFu, m > 1.0f);
            if (lane == 0) masks[(cb * BPB + i) * 4 + wid] = msk;
        }

        // stash x(t+1) into other buffer
        *reinterpret_cast<float4*>(&xs[(nb * BPB + bi_p) * F_DIM + f0_p]) = xn;

        __syncthreads();

        // ---- layer 2: ascending-h1 sparse gather (== dense seq FMA), + b2 after ----
        float c0 = 0.f, c1 = 0.f, c2 = 0.f, c3 = 0.f;
        #pragma unroll
        for (int kw = 0; kw < 4; ++kw) {
            unsigned m = masks[(cb * BPB + wid) * 4 + kw];  // warp-uniform
            while (m) {
                int j = __ffs(m) - 1;
                m &= m - 1;
                const float* col = &W2Ts[(kw * 32 + j) * H_DIM + lane];
                c0 = __fadd_rn(c0, col[0]);
                c1 = __fadd_rn(c1, col[32]);
                c2 = __fadd_rn(c2, col[64]);
                c3 = __fadd_rn(c3, col[96]);
            }
        }
        float cc[4];
        cc[0] = __fadd_rn(c0, b2k[0]);
        cc[1] = __fadd_rn(c1, b2k[1]);
        cc[2] = __fadd_rn(c2, b2k[2]);
        cc[3] = __fadd_rn(c3, b2k[3]);

        // ---- LIF2: unfused update; ballots stay in registers ----
        unsigned m2[4];
        #pragma unroll
        for (int k = 0; k < 4; ++k) {
            float reset = (mem2k[k] > 1.0f) ? 1.0f : 0.0f;
            float bm    = __fmul_rn(beta2k[k], mem2k[k]);
            float m     = __fsub_rn(__fadd_rn(bm, cc[k]), reset);
            mem2k[k] = m;
            m2[k] = __ballot_sync(0xFFFFFFFFu, m > 1.0f);
        }

        // ---- layer 3: ascending-h sparse gather, + b3 after ----
        float o = 0.f;
        #pragma unroll
        for (int k = 0; k < 4; ++k) {
            unsigned m = m2[k];
            while (m) {
                int j = __ffs(m) - 1;
                m &= m - 1;
                o = __fadd_rn(o, W3Ts[(k * 32 + j) * A_DIM + al]);
            }
        }
        o = __fadd_rn(o, b3a);
        if (lane < A_DIM)
            out[((size_t)(bBase + wid) * T_STEPS + t) * A_DIM + lane] = o;
    }
}

extern "C" void kernel_launch(void* const* d_in, const int* in_sizes, int n_in,
                              void* d_out, int out_size) {
    const float* state  = (const float*)d_in[0];  // [512,1024,128]
    const float* hidden = (const float*)d_in[1];  // [512,1,2,128]
    const float* W1     = (const float*)d_in[2];  // [128,128]
    const float* b1     = (const float*)d_in[3];  // [128]
    const float* beta1  = (const float*)d_in[4];  // [128]
    const float* W2     = (const float*)d_in[5];  // [128,128]
    const float* b2     = (const float*)d_in[6];  // [128]
    const float* beta2  = (const float*)d_in[7];  // [128]
    const float* W3     = (const float*)d_in[8];  // [16,128]
    const float* b3     = (const float*)d_in[9];  // [16]
    float* out = (float*)d_out;                   // [512,1024,16]

    cudaFuncSetAttribute(dsqn_kernel,
                         cudaFuncAttributeMaxDynamicSharedMemorySize, SM_BYTES);

    dsqn_kernel<<<NBLOCKS, NTHREADS, SM_BYTES>>>(
        state, hidden, W1, b1, beta1, W2, b2, beta2, W3, b3, out);
}

// round 4
// speedup vs baseline: 1.2336x; 1.2336x over previous
#include <cuda_runtime.h>

// DSQN forward: B=512, T=1024, F=128, H=128, A=16. Faithful fp32.
//
// Numerics contract (bitwise vs JAX fp32 reference — verified rel_err 4.4e-9):
//   cur1 = sequential-f FMA dot (acc starts 0)  THEN  + b1
//   mem  = ((clip(beta)*mem) + cur) - reset   (three separate roundings, no FMA)
//   cur2 = ascending-h1 sum of W2^T cols THEN + b2
//   out  = ascending-h  sum of W3^T cols THEN + b3
//
// R3 structure: 128 blocks x 256 threads, 4 batch/block, 2 batch/thread.
//   thread = (g = tid>>7, h = tid&127); g handles batches {2g, 2g+1}.
//   2 warps per SMSP -> cross-warp latency hiding (R2 had 1, issue=26%).
//   L2/LIF2/L3 on warps 0..3 only (warp w owns batch w); warps 4..7 run
//   ahead into next step's layer 1. One __syncthreads per step.

#define T_STEPS 1024
#define F_DIM   128
#define H_DIM   128
#define A_DIM   16
#define BPB     4
#define BPT     2
#define NTHREADS 256
#define NBLOCKS  128

#define SM_W2T   0
#define SM_W3T   (16384)
#define SM_XS    (16384 + 2048)
#define SM_MASKS (16384 + 2048 + 1024)
#define SM_FLOATS (16384 + 2048 + 1024 + 32)
#define SM_BYTES  (SM_FLOATS * 4)

__global__ __launch_bounds__(NTHREADS, 1)
void dsqn_kernel(const float* __restrict__ state,   // [B,T,F]
                 const float* __restrict__ hidden,  // [B,1,2,H]
                 const float* __restrict__ W1,      // [H,F]
                 const float* __restrict__ b1,      // [H]
                 const float* __restrict__ beta1,   // [H]
                 const float* __restrict__ W2,      // [H,H]
                 const float* __restrict__ b2,      // [H]
                 const float* __restrict__ beta2,   // [H]
                 const float* __restrict__ W3,      // [A,H]
                 const float* __restrict__ b3,      // [A]
                 float* __restrict__ out)           // [B,T,A]
{
    extern __shared__ float sm[];
    float* W2Ts = sm + SM_W2T;
    float* W3Ts = sm + SM_W3T;
    float* xs   = sm + SM_XS;
    unsigned* masks = reinterpret_cast<unsigned*>(sm + SM_MASKS);

    const int tid   = threadIdx.x;
    const int h     = tid & 127;
    const int g     = tid >> 7;          // batch-pair group: 0 or 1
    const int lane  = tid & 31;
    const int wid   = tid >> 5;          // 0..7
    const int bBase = blockIdx.x * BPB;

    // ---- W1 row h into registers (both g groups read same row; L2-broadcast) ----
    float w1r[F_DIM];
    #pragma unroll
    for (int f4 = 0; f4 < 32; ++f4) {
        float4 v = *reinterpret_cast<const float4*>(&W1[h * F_DIM + f4 * 4]);
        w1r[4*f4+0] = v.x; w1r[4*f4+1] = v.y;
        w1r[4*f4+2] = v.z; w1r[4*f4+3] = v.w;
    }

    // ---- per-thread parameters ----
    const float beta1c = fminf(fmaxf(beta1[h], 0.0f), 1.0f);
    const float b1h    = b1[h];

    // layer-2/3 params only used by warps 0..3
    float beta2k[4], b2k[4];
    float mem2k[4];
    const int  al  = lane & 15;
    float b3a = 0.0f;
    if (wid < BPB) {
        #pragma unroll
        for (int k = 0; k < 4; ++k) {
            int hh = lane + 32 * k;
            beta2k[k] = fminf(fmaxf(beta2[hh], 0.0f), 1.0f);
            b2k[k]    = b2[hh];
            mem2k[k]  = hidden[(size_t)(bBase + wid) * 2 * H_DIM + H_DIM + hh];
        }
        b3a = b3[al];
    }

    // ---- mem1: thread (g,h) owns batches 2g, 2g+1 ----
    float mem1[BPT];
    #pragma unroll
    for (int i = 0; i < BPT; ++i)
        mem1[i] = hidden[(size_t)(bBase + 2 * g + i) * 2 * H_DIM + h];

    // ---- W2 transpose into smem (threads with g==0 do it; conflict-free STS) ----
    if (g == 0) {
        #pragma unroll 4
        for (int q = 0; q < 32; ++q) {
            float4 v = *reinterpret_cast<const float4*>(&W2[h * H_DIM + q * 4]);
            W2Ts[(q*4+0) * H_DIM + h] = v.x;
            W2Ts[(q*4+1) * H_DIM + h] = v.y;
            W2Ts[(q*4+2) * H_DIM + h] = v.z;
            W2Ts[(q*4+3) * H_DIM + h] = v.w;
        }
    } else {
        // ---- W3 transpose into smem (g==1 threads) ----
        for (int i = h; i < A_DIM * H_DIM; i += 128) {
            int a  = i >> 7;
            int hh = i & 127;
            W3Ts[hh * A_DIM + a] = W3[i];
        }
    }

    // ---- preload x(t=0): threads 0..127 each load one float4 ----
    const int bi_p = (tid >> 5) & 3;       // batch slot 0..3 (threads 0..127)
    const int f0_p = (tid & 31) * 4;
    if (tid < 128) {
        float4 v = *reinterpret_cast<const float4*>(
            &state[((size_t)(bBase + bi_p) * T_STEPS + 0) * F_DIM + f0_p]);
        *reinterpret_cast<float4*>(&xs[(0 * BPB + bi_p) * F_DIM + f0_p]) = v;
    }
    __syncthreads();

    // ================= main temporal loop =================
    for (int t = 0; t < T_STEPS; ++t) {
        const int cb = t & 1;
        const int nb = cb ^ 1;

        // prefetch x(t+1) (threads 0..127)
        float4 xn = make_float4(0.f, 0.f, 0.f, 0.f);
        if (tid < 128 && t + 1 < T_STEPS)
            xn = *reinterpret_cast<const float4*>(
                &state[((size_t)(bBase + bi_p) * T_STEPS + (t + 1)) * F_DIM + f0_p]);

        // ---- layer 1: sequential-f FMA dot for 2 batch elements ----
        float acc[BPT] = {0.f, 0.f};
        const float* xbase = &xs[cb * BPB * F_DIM + 2 * g * F_DIM];
        #pragma unroll
        for (int f4 = 0; f4 < 32; ++f4) {
            #pragma unroll
            for (int i = 0; i < BPT; ++i) {
                float4 v = *reinterpret_cast<const float4*>(&xbase[i * F_DIM + f4 * 4]);
                acc[i] = fmaf(v.x, w1r[4*f4+0], acc[i]);
                acc[i] = fmaf(v.y, w1r[4*f4+1], acc[i]);
                acc[i] = fmaf(v.z, w1r[4*f4+2], acc[i]);
                acc[i] = fmaf(v.w, w1r[4*f4+3], acc[i]);
            }
        }

        // ---- LIF1: unfused ((beta*mem) + cur) - reset; ballot -> masks ----
        // warp wid covers h chunk (wid&3) for batches {2g, 2g+1}
        #pragma unroll
        for (int i = 0; i < BPT; ++i) {
            float cur   = __fadd_rn(acc[i], b1h);
            float reset = (mem1[i] > 1.0f) ? 1.0f : 0.0f;
            float bm    = __fmul_rn(beta1c, mem1[i]);
            float m     = __fsub_rn(__fadd_rn(bm, cur), reset);
            mem1[i] = m;
            unsigned msk = __ballot_sync(0xFFFFFFFFu, m > 1.0f);
            if (lane == 0) masks[(cb * BPB + 2 * g + i) * 4 + (wid & 3)] = msk;
        }

        // stash x(t+1) into other buffer
        if (tid < 128)
            *reinterpret_cast<float4*>(&xs[(nb * BPB + bi_p) * F_DIM + f0_p]) = xn;

        __syncthreads();

        // ---- layers 2+3 on warps 0..3 (warp w owns batch w); others run ahead ----
        if (wid < BPB) {
            // layer 2: ascending-h1 sparse gather (== dense seq FMA), + b2 after
            float c0 = 0.f, c1 = 0.f, c2 = 0.f, c3 = 0.f;
            #pragma unroll
            for (int kw = 0; kw < 4; ++kw) {
                unsigned m = masks[(cb * BPB + wid) * 4 + kw];  // warp-uniform
                while (m) {
                    int j = __ffs(m) - 1;
                    m &= m - 1;
                    const float* col = &W2Ts[(kw * 32 + j) * H_DIM + lane];
                    c0 = __fadd_rn(c0, col[0]);
                    c1 = __fadd_rn(c1, col[32]);
                    c2 = __fadd_rn(c2, col[64]);
                    c3 = __fadd_rn(c3, col[96]);
                }
            }
            float cc[4];
            cc[0] = __fadd_rn(c0, b2k[0]);
            cc[1] = __fadd_rn(c1, b2k[1]);
            cc[2] = __fadd_rn(c2, b2k[2]);
            cc[3] = __fadd_rn(c3, b2k[3]);

            // LIF2: unfused; ballots stay warp-uniform in registers
            unsigned m2[4];
            #pragma unroll
            for (int k = 0; k < 4; ++k) {
                float reset = (mem2k[k] > 1.0f) ? 1.0f : 0.0f;
                float bm    = __fmul_rn(beta2k[k], mem2k[k]);
                float m     = __fsub_rn(__fadd_rn(bm, cc[k]), reset);
                mem2k[k] = m;
                m2[k] = __ballot_sync(0xFFFFFFFFu, m > 1.0f);
            }

            // layer 3: ascending-h sparse gather, + b3 after
            float o = 0.f;
            #pragma unroll
            for (int k = 0; k < 4; ++k) {
                unsigned m = m2[k];
                while (m) {
                    int j = __ffs(m) - 1;
                    m &= m - 1;
                    o = __fadd_rn(o, W3Ts[(k * 32 + j) * A_DIM + al]);
                }
            }
            o = __fadd_rn(o, b3a);
            if (lane < A_DIM)
                out[((size_t)(bBase + wid) * T_STEPS + t) * A_DIM + lane] = o;
        }
    }
}

extern "C" void kernel_launch(void* const* d_in, const int* in_sizes, int n_in,
                              void* d_out, int out_size) {
    const float* state  = (const float*)d_in[0];  // [512,1024,128]
    const float* hidden = (const float*)d_in[1];  // [512,1,2,128]
    const float* W1     = (const float*)d_in[2];  // [128,128]
    const float* b1     = (const float*)d_in[3];  // [128]
    const float* beta1  = (const float*)d_in[4];  // [128]
    const float* W2     = (const float*)d_in[5];  // [128,128]
    const float* b2     = (const float*)d_in[6];  // [128]
    const float* beta2  = (const float*)d_in[7];  // [128]
    const float* W3     = (const float*)d_in[8];  // [16,128]
    const float* b3     = (const float*)d_in[9];  // [16]
    float* out = (float*)d_out;                   // [512,1024,16]

    cudaFuncSetAttribute(dsqn_kernel,
                         cudaFuncAttributeMaxDynamicSharedMemorySize, SM_BYTES);

    dsqn_kernel<<<NBLOCKS, NTHREADS, SM_BYTES>>>(
        state, hidden, W1, b1, beta1, W2, b2, beta2, W3, b3, out);
}

// round 5
// speedup vs baseline: 1.7724x; 1.4368x over previous
#include <cuda_runtime.h>

// DSQN forward: B=512, T=1024, F=128, H=128, A=16. Faithful fp32.
//
// Numerics contract (verified rel_err 4.4e-9 in R3/R4):
//   cur1 = sequential-k FMA dot (acc starts 0) THEN + b1   [now precomputed]
//   mem  = ((clip(beta)*mem) + cur) - reset   (3 separate roundings, no FMA)
//   cur2 = ascending-h1 sum of W2^T cols THEN + b2
//   out  = ascending-h  sum of W3^T cols THEN + b3
// fma.rn.f32x2: each half is an exact IEEE fp32 fma -> bitwise identical.
//
// R5 structure (decoupled):
//   K1 prep:  W1[n][k] -> g_W1T[k][n]
//   K2 gemm:  g_cur1[m][h] = X[m][:]·W1[h][:] + b1   (m = b*T+t)
//             64x128x128 tiles, 256 thr, 2 blocks/SM, fma.rn.f32x2 n-pairs
//   K3 scan:  128 blocks x 4 warps; warp = one batch element; no barriers
//             in the loop; masks warp-uniform in registers.

#define T_STEPS 1024
#define F_DIM   128
#define H_DIM   128
#define A_DIM   16
#define B_TOT   512
#define M_TOT   (B_TOT * T_STEPS)      // 524288

__device__ float g_cur1[M_TOT * H_DIM];            // 268 MB scratch
__device__ float g_W1T[F_DIM * H_DIM];             // [k][n]

// ---------------- K1: transpose W1 ----------------
__global__ void prep_kernel(const float* __restrict__ W1)  // [H][F] = [n][k]
{
    for (int i = threadIdx.x + blockIdx.x * blockDim.x; i < H_DIM * F_DIM;
         i += blockDim.x * gridDim.x) {
        int n = i >> 7, k = i & 127;
        g_W1T[k * H_DIM + n] = W1[i];
    }
}

// ---------------- K2: layer-1 GEMM (fma.rn.f32x2) ----------------
#define GM_M      64
#define GM_THR    256
#define XS_STRIDE 132                                  // pad: 16B-aligned rows, 4-way LDS ok
#define GEMM_SMEM ((F_DIM * H_DIM + GM_M * XS_STRIDE) * 4)   // 64KB + 33KB

__global__ __launch_bounds__(GM_THR, 2)
void gemm_kernel(const float* __restrict__ state,    // [M][K]
                 const float* __restrict__ b1)       // [N]
{
    extern __shared__ float sg[];
    float* w1t_s = sg;                         // [k][n]  128*128
    float* x_s   = sg + F_DIM * H_DIM;         // [m][k]  64*132

    const int tid  = threadIdx.x;
    const int lane = tid & 31;
    const int wrp  = tid >> 5;                 // 0..7
    const int m0   = blockIdx.x * GM_M;
    const int n0   = wrp * 16;

    // load W1T (coalesced, conflict-free)
    #pragma unroll 4
    for (int i = tid; i < (F_DIM * H_DIM) / 4; i += GM_THR)
        reinterpret_cast<float4*>(w1t_s)[i] =
            reinterpret_cast<const float4*>(g_W1T)[i];
    // load X tile rows m0..m0+63 (coalesced LDG.128, conflict-free STS.128)
    #pragma unroll 2
    for (int i = tid; i < GM_M * 32; i += GM_THR) {
        int m = i >> 5, k4 = i & 31;
        float4 v = reinterpret_cast<const float4*>(state)[(size_t)(m0 + m) * 32 + k4];
        *reinterpret_cast<float4*>(&x_s[m * XS_STRIDE + 4 * k4]) = v;
    }
    __syncthreads();

    // acc pairs: a[mi][j] covers (m = lane+32*mi, n = n0+2j, n0+2j+1)
    unsigned long long a0[8], a1[8];
    #pragma unroll
    for (int j = 0; j < 8; ++j) { a0[j] = 0ull; a1[j] = 0ull; }

    const float* xr0 = &x_s[lane * XS_STRIDE];
    const float* xr1 = &x_s[(lane + 32) * XS_STRIDE];

    #pragma unroll 8
    for (int k = 0; k < F_DIM; ++k) {
        float x0 = xr0[k], x1 = xr1[k];
        unsigned long long px0, px1;
        asm("mov.b64 %0, {%1, %1};" : "=l"(px0) : "f"(x0));
        asm("mov.b64 %0, {%1, %1};" : "=l"(px1) : "f"(x1));
        const ulonglong2* wp =
            reinterpret_cast<const ulonglong2*>(&w1t_s[k * H_DIM + n0]);
        #pragma unroll
        for (int j2 = 0; j2 < 4; ++j2) {
            ulonglong2 w2 = wp[j2];                     // LDS.128 (broadcast)
            asm("fma.rn.f32x2 %0, %1, %2, %0;" : "+l"(a0[2*j2  ]) : "l"(px0), "l"(w2.x));
            asm("fma.rn.f32x2 %0, %1, %2, %0;" : "+l"(a0[2*j2+1]) : "l"(px0), "l"(w2.y));
            asm("fma.rn.f32x2 %0, %1, %2, %0;" : "+l"(a1[2*j2  ]) : "l"(px1), "l"(w2.x));
            asm("fma.rn.f32x2 %0, %1, %2, %0;" : "+l"(a1[2*j2+1]) : "l"(px1), "l"(w2.y));
        }
    }

    // epilogue: + b1 (separate rounding), store [m][n0..n0+15]
    float bn[16];
    #pragma unroll
    for (int j = 0; j < 16; ++j) bn[j] = b1[n0 + j];

    #pragma unroll
    for (int mi = 0; mi < 2; ++mi) {
        const unsigned long long* ap = mi ? a1 : a0;
        size_t mg = (size_t)(m0 + lane + 32 * mi);
        #pragma unroll
        for (int j2 = 0; j2 < 4; ++j2) {
            float f0, f1, f2, f3;
            asm("mov.b64 {%0, %1}, %2;" : "=f"(f0), "=f"(f1) : "l"(ap[2*j2]));
            asm("mov.b64 {%0, %1}, %2;" : "=f"(f2), "=f"(f3) : "l"(ap[2*j2+1]));
            float4 o;
            o.x = __fadd_rn(f0, bn[4*j2+0]);
            o.y = __fadd_rn(f1, bn[4*j2+1]);
            o.z = __fadd_rn(f2, bn[4*j2+2]);
            o.w = __fadd_rn(f3, bn[4*j2+3]);
            reinterpret_cast<float4*>(g_cur1)[mg * 32 + (n0 >> 2) + j2] = o;
        }
    }
}

// ---------------- K3: scan (warp = batch element, no loop barriers) ----------------
#define SC_THR    128
#define SC_BLOCKS 128
#define SM_W2T    0
#define SM_W3T    (H_DIM * H_DIM)
#define SCAN_SMEM ((H_DIM * H_DIM + H_DIM * A_DIM) * 4)   // 72 KB

__global__ __launch_bounds__(SC_THR, 1)
void scan_kernel(const float* __restrict__ hidden,  // [B][1][2][H]
                 const float* __restrict__ W2,      // [H][H]
                 const float* __restrict__ b2,
                 const float* __restrict__ beta1,
                 const float* __restrict__ beta2,
                 const float* __restrict__ W3,      // [A][H]
                 const float* __restrict__ b3,
                 float* __restrict__ out)           // [B][T][A]
{
    extern __shared__ float sm[];
    float* W2Ts = sm + SM_W2T;                 // [h1][h]
    float* W3Ts = sm + SM_W3T;                 // [h][a]

    const int tid  = threadIdx.x;
    const int lane = tid & 31;
    const int wid  = tid >> 5;                 // 0..3, warp = batch slot
    const int b    = blockIdx.x * 4 + wid;
    const int al   = lane & 15;

    // W2 transpose into smem: thread h reads its row, conflict-free STS
    {
        const int h = tid;
        #pragma unroll 4
        for (int q = 0; q < 32; ++q) {
            float4 v = *reinterpret_cast<const float4*>(&W2[h * H_DIM + q * 4]);
            W2Ts[(q*4+0) * H_DIM + h] = v.x;
            W2Ts[(q*4+1) * H_DIM + h] = v.y;
            W2Ts[(q*4+2) * H_DIM + h] = v.z;
            W2Ts[(q*4+3) * H_DIM + h] = v.w;
        }
        for (int i = tid; i < A_DIM * H_DIM; i += SC_THR) {
            int a2 = i >> 7, hh = i & 127;
            W3Ts[hh * A_DIM + a2] = W3[i];
        }
    }

    // per-lane parameters / state: lane owns h = lane + 32k
    float beta1k[4], beta2k[4], b2k[4], mem1[4], mem2[4];
    #pragma unroll
    for (int k = 0; k < 4; ++k) {
        int hh = lane + 32 * k;
        beta1k[k] = fminf(fmaxf(beta1[hh], 0.0f), 1.0f);
        beta2k[k] = fminf(fmaxf(beta2[hh], 0.0f), 1.0f);
        b2k[k]    = b2[hh];
        mem1[k]   = hidden[(size_t)b * 2 * H_DIM + hh];
        mem2[k]   = hidden[(size_t)b * 2 * H_DIM + H_DIM + hh];
    }
    const float b3a = b3[al];

    __syncthreads();   // smem tables ready; no barriers after this

    const float* curbase = g_cur1 + (size_t)b * T_STEPS * H_DIM;
    float* outbase = out + (size_t)b * T_STEPS * A_DIM;

    // preload cur1(t=0)
    float ccur[4];
    #pragma unroll
    for (int k = 0; k < 4; ++k) ccur[k] = curbase[lane + 32 * k];

    for (int t = 0; t < T_STEPS; ++t) {
        // prefetch cur1(t+1)
        float cnxt[4] = {0.f, 0.f, 0.f, 0.f};
        if (t + 1 < T_STEPS) {
            const float* p = curbase + (size_t)(t + 1) * H_DIM;
            #pragma unroll
            for (int k = 0; k < 4; ++k) cnxt[k] = p[lane + 32 * k];
        }

        // LIF1 (cur already includes b1): ((beta*mem)+cur)-reset; ballots
        unsigned m1[4];
        #pragma unroll
        for (int k = 0; k < 4; ++k) {
            float reset = (mem1[k] > 1.0f) ? 1.0f : 0.0f;
            float bm    = __fmul_rn(beta1k[k], mem1[k]);
            float m     = __fsub_rn(__fadd_rn(bm, ccur[k]), reset);
            mem1[k] = m;
            m1[k] = __ballot_sync(0xFFFFFFFFu, m > 1.0f);
        }

        // layer 2: ascending-h1 sparse gather, + b2 after
        float c0 = 0.f, c1 = 0.f, c2 = 0.f, c3 = 0.f;
        #pragma unroll
        for (int kw = 0; kw < 4; ++kw) {
            unsigned m = m1[kw];                       // warp-uniform
            while (m) {
                int j = __ffs(m) - 1;
                m &= m - 1;
                const float* col = &W2Ts[(kw * 32 + j) * H_DIM + lane];
                c0 = __fadd_rn(c0, col[0]);
                c1 = __fadd_rn(c1, col[32]);
                c2 = __fadd_rn(c2, col[64]);
                c3 = __fadd_rn(c3, col[96]);
            }
        }
        float cc[4];
        cc[0] = __fadd_rn(c0, b2k[0]);
        cc[1] = __fadd_rn(c1, b2k[1]);
        cc[2] = __fadd_rn(c2, b2k[2]);
        cc[3] = __fadd_rn(c3, b2k[3]);

        // LIF2
        unsigned m2[4];
        #pragma unroll
        for (int k = 0; k < 4; ++k) {
            float reset = (mem2[k] > 1.0f) ? 1.0f : 0.0f;
            float bm    = __fmul_rn(beta2k[k], mem2[k]);
            float m     = __fsub_rn(__fadd_rn(bm, cc[k]), reset);
            mem2[k] = m;
            m2[k] = __ballot_sync(0xFFFFFFFFu, m > 1.0f);
        }

        // layer 3: ascending-h sparse gather, + b3 after
        float o = 0.f;
        #pragma unroll
        for (int k = 0; k < 4; ++k) {
            unsigned m = m2[k];
            while (m) {
                int j = __ffs(m) - 1;
                m &= m - 1;
                o = __fadd_rn(o, W3Ts[(k * 32 + j) * A_DIM + al]);
            }
        }
        o = __fadd_rn(o, b3a);
        if (lane < A_DIM)
            outbase[(size_t)t * A_DIM + lane] = o;

        #pragma unroll
        for (int k = 0; k < 4; ++k) ccur[k] = cnxt[k];
    }
}

extern "C" void kernel_launch(void* const* d_in, const int* in_sizes, int n_in,
                              void* d_out, int out_size) {
    const float* state  = (const float*)d_in[0];  // [512,1024,128]
    const float* hidden = (const float*)d_in[1];  // [512,1,2,128]
    const float* W1     = (const float*)d_in[2];  // [128,128]
    const float* b1     = (const float*)d_in[3];  // [128]
    const float* beta1  = (const float*)d_in[4];  // [128]
    const float* W2     = (const float*)d_in[5];  // [128,128]
    const float* b2     = (const float*)d_in[6];  // [128]
    const float* beta2  = (const float*)d_in[7];  // [128]
    const float* W3     = (const float*)d_in[8];  // [16,128]
    const float* b3     = (const float*)d_in[9];  // [16]
    float* out = (float*)d_out;                   // [512,1024,16]

    cudaFuncSetAttribute(gemm_kernel,
                         cudaFuncAttributeMaxDynamicSharedMemorySize, GEMM_SMEM);
    cudaFuncSetAttribute(scan_kernel,
                         cudaFuncAttributeMaxDynamicSharedMemorySize, SCAN_SMEM);

    prep_kernel<<<32, 256>>>(W1);
    gemm_kernel<<<M_TOT / GM_M, GM_THR, GEMM_SMEM>>>(state, b1);
    scan_kernel<<<SC_BLOCKS, SC_THR, SCAN_SMEM>>>(hidden, W2, b2, beta1, beta2,
                                                  W3, b3, out);
}

// round 6
// speedup vs baseline: 2.0219x; 1.1407x over previous
#include <cuda_runtime.h>

// DSQN forward: B=512, T=1024, F=128, H=128, A=16. Faithful fp32.
//
// Numerics contract (verified rel_err 4.4e-9):
//   cur1 = sequential-k FMA dot (acc starts 0) THEN + b1   [precomputed]
//   mem  = ((clip(beta)*mem) + cur) - reset   (3 separate roundings, no FMA)
//   cur2 = ascending-h1 sum of W2^T cols THEN + b2
//   out  = ascending-h  sum of W3^T cols THEN + b3
// fma.rn.f32x2: each half is an exact IEEE fp32 fma -> bitwise identical.
//
// R6 changes (scan only; GEMM at fma floor):
//   - layer 3 pipelined one step behind (its serial FADD chain no longer on
//     the recurrence critical path; interleaves with LIF1/gather of step t)
//   - cur1 prefetch depth 4 (t-loop unrolled x4, rolling register buffer)
//   - W2Ts stored [h1][lane][j] -> gather is one LDS.128 per spike

#define T_STEPS 1024
#define F_DIM   128
#define H_DIM   128
#define A_DIM   16
#define B_TOT   512
#define M_TOT   (B_TOT * T_STEPS)      // 524288

__device__ float g_cur1[M_TOT * H_DIM];            // 268 MB scratch
__device__ float g_W1T[F_DIM * H_DIM];             // [k][n]

// ---------------- K1: transpose W1 ----------------
__global__ void prep_kernel(const float* __restrict__ W1)  // [H][F] = [n][k]
{
    for (int i = threadIdx.x + blockIdx.x * blockDim.x; i < H_DIM * F_DIM;
         i += blockDim.x * gridDim.x) {
        int n = i >> 7, k = i & 127;
        g_W1T[k * H_DIM + n] = W1[i];
    }
}

// ---------------- K2: layer-1 GEMM (fma.rn.f32x2) ----------------
#define GM_M      64
#define GM_THR    256
#define XS_STRIDE 132
#define GEMM_SMEM ((F_DIM * H_DIM + GM_M * XS_STRIDE) * 4)

__global__ __launch_bounds__(GM_THR, 2)
void gemm_kernel(const float* __restrict__ state,    // [M][K]
                 const float* __restrict__ b1)       // [N]
{
    extern __shared__ float sg[];
    float* w1t_s = sg;                         // [k][n]  128*128
    float* x_s   = sg + F_DIM * H_DIM;         // [m][k]  64*132

    const int tid  = threadIdx.x;
    const int lane = tid & 31;
    const int wrp  = tid >> 5;
    const int m0   = blockIdx.x * GM_M;
    const int n0   = wrp * 16;

    #pragma unroll 4
    for (int i = tid; i < (F_DIM * H_DIM) / 4; i += GM_THR)
        reinterpret_cast<float4*>(w1t_s)[i] =
            reinterpret_cast<const float4*>(g_W1T)[i];
    #pragma unroll 2
    for (int i = tid; i < GM_M * 32; i += GM_THR) {
        int m = i >> 5, k4 = i & 31;
        float4 v = reinterpret_cast<const float4*>(state)[(size_t)(m0 + m) * 32 + k4];
        *reinterpret_cast<float4*>(&x_s[m * XS_STRIDE + 4 * k4]) = v;
    }
    __syncthreads();

    unsigned long long a0[8], a1[8];
    #pragma unroll
    for (int j = 0; j < 8; ++j) { a0[j] = 0ull; a1[j] = 0ull; }

    const float* xr0 = &x_s[lane * XS_STRIDE];
    const float* xr1 = &x_s[(lane + 32) * XS_STRIDE];

    #pragma unroll 8
    for (int k = 0; k < F_DIM; ++k) {
        float x0 = xr0[k], x1 = xr1[k];
        unsigned long long px0, px1;
        asm("mov.b64 %0, {%1, %1};" : "=l"(px0) : "f"(x0));
        asm("mov.b64 %0, {%1, %1};" : "=l"(px1) : "f"(x1));
        const ulonglong2* wp =
            reinterpret_cast<const ulonglong2*>(&w1t_s[k * H_DIM + n0]);
        #pragma unroll
        for (int j2 = 0; j2 < 4; ++j2) {
            ulonglong2 w2 = wp[j2];
            asm("fma.rn.f32x2 %0, %1, %2, %0;" : "+l"(a0[2*j2  ]) : "l"(px0), "l"(w2.x));
            asm("fma.rn.f32x2 %0, %1, %2, %0;" : "+l"(a0[2*j2+1]) : "l"(px0), "l"(w2.y));
            asm("fma.rn.f32x2 %0, %1, %2, %0;" : "+l"(a1[2*j2  ]) : "l"(px1), "l"(w2.x));
            asm("fma.rn.f32x2 %0, %1, %2, %0;" : "+l"(a1[2*j2+1]) : "l"(px1), "l"(w2.y));
        }
    }

    float bn[16];
    #pragma unroll
    for (int j = 0; j < 16; ++j) bn[j] = b1[n0 + j];

    #pragma unroll
    for (int mi = 0; mi < 2; ++mi) {
        const unsigned long long* ap = mi ? a1 : a0;
        size_t mg = (size_t)(m0 + lane + 32 * mi);
        #pragma unroll
        for (int j2 = 0; j2 < 4; ++j2) {
            float f0, f1, f2, f3;
            asm("mov.b64 {%0, %1}, %2;" : "=f"(f0), "=f"(f1) : "l"(ap[2*j2]));
            asm("mov.b64 {%0, %1}, %2;" : "=f"(f2), "=f"(f3) : "l"(ap[2*j2+1]));
            float4 o;
            o.x = __fadd_rn(f0, bn[4*j2+0]);
            o.y = __fadd_rn(f1, bn[4*j2+1]);
            o.z = __fadd_rn(f2, bn[4*j2+2]);
            o.w = __fadd_rn(f3, bn[4*j2+3]);
            reinterpret_cast<float4*>(g_cur1)[mg * 32 + (n0 >> 2) + j2] = o;
        }
    }
}

// ---------------- K3: scan (warp = batch element, no loop barriers) ----------------
#define SC_THR    128
#define SC_BLOCKS 128
#define SM_W2T    0
#define SM_W3T    (H_DIM * H_DIM)
#define SCAN_SMEM ((H_DIM * H_DIM + H_DIM * A_DIM) * 4)   // 72 KB

__global__ __launch_bounds__(SC_THR, 1)
void scan_kernel(const float* __restrict__ hidden,  // [B][1][2][H]
                 const float* __restrict__ W2,      // [H][H]
                 const float* __restrict__ b2,
                 const float* __restrict__ beta1,
                 const float* __restrict__ beta2,
                 const float* __restrict__ W3,      // [A][H]
                 const float* __restrict__ b3,
                 float* __restrict__ out)           // [B][T][A]
{
    extern __shared__ float sm[];
    float* W2Ts = sm + SM_W2T;   // [h1][lane][j]: W2Ts[h1*128 + (h&31)*4 + (h>>5)] = W2[h][h1]
    float* W3Ts = sm + SM_W3T;   // [h][a]

    const int tid  = threadIdx.x;
    const int lane = tid & 31;
    const int wid  = tid >> 5;                 // warp = batch slot 0..3
    const int b    = blockIdx.x * 4 + wid;
    const int al   = lane & 15;

    // W2 into smem, layout [h1][lane][j]; thread h reads row h of W2
    {
        const int h = tid;
        const int base = (h & 31) * 4 + (h >> 5);
        #pragma unroll 4
        for (int q = 0; q < 32; ++q) {
            float4 v = *reinterpret_cast<const float4*>(&W2[h * H_DIM + q * 4]);
            W2Ts[(q*4+0) * H_DIM + base] = v.x;
            W2Ts[(q*4+1) * H_DIM + base] = v.y;
            W2Ts[(q*4+2) * H_DIM + base] = v.z;
            W2Ts[(q*4+3) * H_DIM + base] = v.w;
        }
        for (int i = tid; i < A_DIM * H_DIM; i += SC_THR) {
            int a2 = i >> 7, hh = i & 127;
            W3Ts[hh * A_DIM + a2] = W3[i];
        }
    }

    // per-lane params/state: lane owns h = lane + 32k (k = chain index)
    float beta1k[4], beta2k[4], b2k[4], mem1[4], mem2[4];
    #pragma unroll
    for (int k = 0; k < 4; ++k) {
        int hh = lane + 32 * k;
        beta1k[k] = fminf(fmaxf(beta1[hh], 0.0f), 1.0f);
        beta2k[k] = fminf(fmaxf(beta2[hh], 0.0f), 1.0f);
        b2k[k]    = b2[hh];
        mem1[k]   = hidden[(size_t)b * 2 * H_DIM + hh];
        mem2[k]   = hidden[(size_t)b * 2 * H_DIM + H_DIM + hh];
    }
    const float b3a = b3[al];

    __syncthreads();   // smem tables ready; no barriers after this

    const float* curbase = g_cur1 + (size_t)b * T_STEPS * H_DIM;
    float* outbase = out + (size_t)b * T_STEPS * A_DIM;

    // rolling prefetch buffer: fcur[u] holds cur1(tb+u); depth 4
    float fcur[4][4];
    #pragma unroll
    for (int u = 0; u < 4; ++u)
        #pragma unroll
        for (int k = 0; k < 4; ++k)
            fcur[u][k] = curbase[(size_t)u * H_DIM + lane + 32 * k];

    unsigned m2s[4] = {0u, 0u, 0u, 0u};   // spk2 masks of step t-1

    for (int tb = 0; tb < T_STEPS; tb += 4) {
        #pragma unroll
        for (int u = 0; u < 4; ++u) {
            const int t = tb + u;

            // prefetch cur1(t+4) into this slot's replacement
            float pre[4] = {0.f, 0.f, 0.f, 0.f};
            if (t + 4 < T_STEPS) {
                const float* p = curbase + (size_t)(t + 4) * H_DIM;
                #pragma unroll
                for (int k = 0; k < 4; ++k) pre[k] = p[lane + 32 * k];
            }

            // ---- layer 3 for step t-1 (off critical path; interleaves) ----
            if (t > 0) {
                float o = 0.f;
                #pragma unroll
                for (int k = 0; k < 4; ++k) {
                    unsigned m = m2s[k];
                    while (m) {
                        int j = __ffs(m) - 1;
                        m &= m - 1;
                        o = __fadd_rn(o, W3Ts[(k * 32 + j) * A_DIM + al]);
                    }
                }
                o = __fadd_rn(o, b3a);
                if (lane < A_DIM)
                    outbase[(size_t)(t - 1) * A_DIM + lane] = o;
            }

            // ---- LIF1 (cur includes b1): ((beta*mem)+cur)-reset; ballots ----
            unsigned m1[4];
            #pragma unroll
            for (int k = 0; k < 4; ++k) {
                float reset = (mem1[k] > 1.0f) ? 1.0f : 0.0f;
                float bm    = __fmul_rn(beta1k[k], mem1[k]);
                float m     = __fsub_rn(__fadd_rn(bm, fcur[u][k]), reset);
                mem1[k] = m;
                m1[k] = __ballot_sync(0xFFFFFFFFu, m > 1.0f);
            }

            // ---- layer 2: ascending-h1 gather, LDS.128 per spike, + b2 after ----
            float c0 = 0.f, c1 = 0.f, c2 = 0.f, c3 = 0.f;
            #pragma unroll
            for (int kw = 0; kw < 4; ++kw) {
                unsigned m = m1[kw];                   // warp-uniform
                while (m) {
                    int j = __ffs(m) - 1;
                    m &= m - 1;
                    float4 v = *reinterpret_cast<const float4*>(
                        &W2Ts[(kw * 32 + j) * H_DIM + lane * 4]);
                    c0 = __fadd_rn(c0, v.x);
                    c1 = __fadd_rn(c1, v.y);
                    c2 = __fadd_rn(c2, v.z);
                    c3 = __fadd_rn(c3, v.w);
                }
            }
            float cc[4];
            cc[0] = __fadd_rn(c0, b2k[0]);
            cc[1] = __fadd_rn(c1, b2k[1]);
            cc[2] = __fadd_rn(c2, b2k[2]);
            cc[3] = __fadd_rn(c3, b2k[3]);

            // ---- LIF2; masks saved for next iteration's layer 3 ----
            #pragma unroll
            for (int k = 0; k < 4; ++k) {
                float reset = (mem2[k] > 1.0f) ? 1.0f : 0.0f;
                float bm    = __fmul_rn(beta2k[k], mem2[k]);
                float m     = __fsub_rn(__fadd_rn(bm, cc[k]), reset);
                mem2[k] = m;
                m2s[k] = __ballot_sync(0xFFFFFFFFu, m > 1.0f);
            }

            // rotate prefetch slot
            #pragma unroll
            for (int k = 0; k < 4; ++k) fcur[u][k] = pre[k];
        }
    }

    // epilogue: layer 3 for t = T-1
    {
        float o = 0.f;
        #pragma unroll
        for (int k = 0; k < 4; ++k) {
            unsigned m = m2s[k];
            while (m) {
                int j = __ffs(m) - 1;
                m &= m - 1;
                o = __fadd_rn(o, W3Ts[(k * 32 + j) * A_DIM + al]);
            }
        }
        o = __fadd_rn(o, b3a);
        if (lane < A_DIM)
            outbase[(size_t)(T_STEPS - 1) * A_DIM + lane] = o;
    }
}

extern "C" void kernel_launch(void* const* d_in, const int* in_sizes, int n_in,
                              void* d_out, int out_size) {
    const float* state  = (const float*)d_in[0];  // [512,1024,128]
    const float* hidden = (const float*)d_in[1];  // [512,1,2,128]
    const float* W1     = (const float*)d_in[2];  // [128,128]
    const float* b1     = (const float*)d_in[3];  // [128]
    const float* beta1  = (const float*)d_in[4];  // [128]
    const float* W2     = (const float*)d_in[5];  // [128,128]
    const float* b2     = (const float*)d_in[6];  // [128]
    const float* beta2  = (const float*)d_in[7];  // [128]
    const float* W3     = (const float*)d_in[8];  // [16,128]
    const float* b3     = (const float*)d_in[9];  // [16]
    float* out = (float*)d_out;                   // [512,1024,16]

    cudaFuncSetAttribute(gemm_kernel,
                         cudaFuncAttributeMaxDynamicSharedMemorySize, GEMM_SMEM);
    cudaFuncSetAttribute(scan_kernel,
                         cudaFuncAttributeMaxDynamicSharedMemorySize, SCAN_SMEM);

    prep_kernel<<<32, 256>>>(W1);
    gemm_kernel<<<M_TOT / GM_M, GM_THR, GEMM_SMEM>>>(state, b1);
    scan_kernel<<<SC_BLOCKS, SC_THR, SCAN_SMEM>>>(hidden, W2, b2, beta1, beta2,
                                                  W3, b3, out);
}

// round 7
// speedup vs baseline: 2.3826x; 1.1784x over previous
#include <cuda_runtime.h>
#include <cstdint>

// DSQN forward: B=512, T=1024, F=128, H=128, A=16. Faithful fp32.
//
// Numerics contract (verified rel_err 4.4e-9):
//   cur1 = sequential-k FMA dot (acc 0) THEN + b1      [GEMM, f32x2 exact]
//   mem  = ((clip(beta)*mem) + cur) - reset            (3 separate roundings)
//   cur2 = ascending-h1 sum of W2^T cols THEN + b2     (bitwise = dense seq-k)
//   out  = sum of W3 cols THEN + b3  (order permuted: output-only rounding)
//
// R7 restructure — scans are per-neuron independent; cur2 is t-parallel:
//   prep : W1T, W2p ([h1][perm(h2)]), W3p ([p][a])
//   gemm : cur1[m][h]                          (fma.rn.f32x2, at fma floor)
//   lif1 : 65536 scalar scans -> masks1        (2048 warps)
//   cur2 : sparse gather per (b,t), full chip  (branches hidden by occupancy)
//   lif2 : 65536 scalar scans -> masks2
//   outk : sparse W3 gather per (b,t), full chip

#define T_STEPS 1024
#define F_DIM   128
#define H_DIM   128
#define A_DIM   16
#define B_TOT   512
#define M_TOT   (B_TOT * T_STEPS)      // 524288

__device__ float g_cur1[M_TOT * H_DIM];            // 268 MB
__device__ float g_cur2[M_TOT * H_DIM];            // 268 MB (permuted h2: p)
__device__ float g_W1T[F_DIM * H_DIM];             // [k][n]
__device__ float g_W2p[H_DIM * H_DIM];             // [h1][(h2&31)*4+(h2>>5)]
__device__ float g_W3p[H_DIM * A_DIM];             // [p][a], h2(p)=(p>>2)+32*(p&3)
__device__ uint4 g_m1[M_TOT];                      // spk1 masks per (b,t)
__device__ uint4 g_m2[M_TOT];                      // spk2 masks per (b,t)

// ---------------- prep: weight layouts ----------------
__global__ void prep_kernel(const float* __restrict__ W1,
                            const float* __restrict__ W2,
                            const float* __restrict__ W3)
{
    int i = threadIdx.x + blockIdx.x * blockDim.x;
    if (i < H_DIM * F_DIM) {
        int n = i >> 7, k = i & 127;
        g_W1T[k * H_DIM + n] = W1[i];                 // W1T[k][n]
        int h2 = n, h1 = k;                           // i = h2*128 + h1
        g_W2p[h1 * H_DIM + (h2 & 31) * 4 + (h2 >> 5)] = W2[i];
    }
    if (i < H_DIM * A_DIM) {
        int p = i >> 4, a = i & 15;
        int h2 = (p >> 2) + 32 * (p & 3);
        g_W3p[p * A_DIM + a] = W3[a * H_DIM + h2];
    }
}

// ---------------- gemm: cur1 = X @ W1^T + b1 (fma.rn.f32x2) ----------------
#define GM_M      64
#define GM_THR    256
#define XS_STRIDE 132
#define GEMM_SMEM ((F_DIM * H_DIM + GM_M * XS_STRIDE) * 4)

__global__ __launch_bounds__(GM_THR, 2)
void gemm_kernel(const float* __restrict__ state, const float* __restrict__ b1)
{
    extern __shared__ float sg[];
    float* w1t_s = sg;
    float* x_s   = sg + F_DIM * H_DIM;

    const int tid  = threadIdx.x;
    const int lane = tid & 31;
    const int wrp  = tid >> 5;
    const int m0   = blockIdx.x * GM_M;
    const int n0   = wrp * 16;

    #pragma unroll 4
    for (int i = tid; i < (F_DIM * H_DIM) / 4; i += GM_THR)
        reinterpret_cast<float4*>(w1t_s)[i] =
            reinterpret_cast<const float4*>(g_W1T)[i];
    #pragma unroll 2
    for (int i = tid; i < GM_M * 32; i += GM_THR) {
        int m = i >> 5, k4 = i & 31;
        float4 v = reinterpret_cast<const float4*>(state)[(size_t)(m0 + m) * 32 + k4];
        *reinterpret_cast<float4*>(&x_s[m * XS_STRIDE + 4 * k4]) = v;
    }
    __syncthreads();

    unsigned long long a0[8], a1[8];
    #pragma unroll
    for (int j = 0; j < 8; ++j) { a0[j] = 0ull; a1[j] = 0ull; }

    const float* xr0 = &x_s[lane * XS_STRIDE];
    const float* xr1 = &x_s[(lane + 32) * XS_STRIDE];

    #pragma unroll 8
    for (int k = 0; k < F_DIM; ++k) {
        float x0 = xr0[k], x1 = xr1[k];
        unsigned long long px0, px1;
        asm("mov.b64 %0, {%1, %1};" : "=l"(px0) : "f"(x0));
        asm("mov.b64 %0, {%1, %1};" : "=l"(px1) : "f"(x1));
        const ulonglong2* wp =
            reinterpret_cast<const ulonglong2*>(&w1t_s[k * H_DIM + n0]);
        #pragma unroll
        for (int j2 = 0; j2 < 4; ++j2) {
            ulonglong2 w2 = wp[j2];
            asm("fma.rn.f32x2 %0, %1, %2, %0;" : "+l"(a0[2*j2  ]) : "l"(px0), "l"(w2.x));
            asm("fma.rn.f32x2 %0, %1, %2, %0;" : "+l"(a0[2*j2+1]) : "l"(px0), "l"(w2.y));
            asm("fma.rn.f32x2 %0, %1, %2, %0;" : "+l"(a1[2*j2  ]) : "l"(px1), "l"(w2.x));
            asm("fma.rn.f32x2 %0, %1, %2, %0;" : "+l"(a1[2*j2+1]) : "l"(px1), "l"(w2.y));
        }
    }

    float bn[16];
    #pragma unroll
    for (int j = 0; j < 16; ++j) bn[j] = b1[n0 + j];

    #pragma unroll
    for (int mi = 0; mi < 2; ++mi) {
        const unsigned long long* ap = mi ? a1 : a0;
        size_t mg = (size_t)(m0 + lane + 32 * mi);
        #pragma unroll
        for (int j2 = 0; j2 < 4; ++j2) {
            float f0, f1, f2, f3;
            asm("mov.b64 {%0, %1}, %2;" : "=f"(f0), "=f"(f1) : "l"(ap[2*j2]));
            asm("mov.b64 {%0, %1}, %2;" : "=f"(f2), "=f"(f3) : "l"(ap[2*j2+1]));
            float4 o;
            o.x = __fadd_rn(f0, bn[4*j2+0]);
            o.y = __fadd_rn(f1, bn[4*j2+1]);
            o.z = __fadd_rn(f2, bn[4*j2+2]);
            o.w = __fadd_rn(f3, bn[4*j2+3]);
            reinterpret_cast<float4*>(g_cur1)[mg * 32 + (n0 >> 2) + j2] = o;
        }
    }
}

// ---------------- lif1: 65536 scalar scans -> masks1 ----------------
// warp = (b, g); lane handles h = g*32+lane. Unrolled x8 with prefetch.
__global__ __launch_bounds__(256, 4)
void lif1_kernel(const float* __restrict__ hidden, const float* __restrict__ beta1)
{
    const int lane = threadIdx.x & 31;
    const int wg   = blockIdx.x * 8 + (threadIdx.x >> 5);
    const int b    = wg >> 2, g = wg & 3;
    const int h    = g * 32 + lane;

    const float beta = fminf(fmaxf(beta1[h], 0.0f), 1.0f);
    float mem = hidden[(size_t)b * 2 * H_DIM + h];
    const float* cb = g_cur1 + (size_t)b * T_STEPS * H_DIM + h;
    unsigned* mout = reinterpret_cast<unsigned*>(g_m1) + (size_t)b * T_STEPS * 4 + g;

    float cur[8], nxt[8];
    #pragma unroll
    for (int i = 0; i < 8; ++i) cur[i] = cb[(size_t)i * H_DIM];

    for (int t0 = 0; t0 < T_STEPS; t0 += 8) {
        if (t0 + 8 < T_STEPS) {
            #pragma unroll
            for (int i = 0; i < 8; ++i) nxt[i] = cb[(size_t)(t0 + 8 + i) * H_DIM];
        }
        #pragma unroll
        for (int u = 0; u < 8; ++u) {
            float reset = (mem > 1.0f) ? 1.0f : 0.0f;
            float m = __fsub_rn(__fadd_rn(__fmul_rn(beta, mem), cur[u]), reset);
            mem = m;
            unsigned msk = __ballot_sync(0xFFFFFFFFu, m > 1.0f);
            if (lane == 0) mout[(size_t)(t0 + u) * 4] = msk;
        }
        #pragma unroll
        for (int i = 0; i < 8; ++i) cur[i] = nxt[i];
    }
}

// ---------------- cur2: sparse gather per (b,t), full chip ----------------
// warp handles 16 consecutive t of one b; lane's chains j: h2 = lane+32j -> p = lane*4+j
#define C2_SMEM (H_DIM * H_DIM * 4)   // 64 KB W2p table

__global__ __launch_bounds__(256, 3)
void cur2_kernel(const float* __restrict__ b2)
{
    extern __shared__ float w2s[];
    const int tid  = threadIdx.x;
    const int lane = tid & 31;

    #pragma unroll 4
    for (int i = tid; i < (H_DIM * H_DIM) / 4; i += 256)
        reinterpret_cast<float4*>(w2s)[i] =
            reinterpret_cast<const float4*>(g_W2p)[i];

    float b2j[4];
    #pragma unroll
    for (int j = 0; j < 4; ++j) b2j[j] = b2[lane + 32 * j];
    __syncthreads();

    const int W  = blockIdx.x * 8 + (tid >> 5);
    const int b  = W >> 6;
    const int t0 = (W & 63) * 16;
    const size_t base = (size_t)b * T_STEPS + t0;

    uint4 mk = g_m1[base];
    #pragma unroll 2
    for (int tt = 0; tt < 16; ++tt) {
        uint4 nk = (tt + 1 < 16) ? g_m1[base + tt + 1] : make_uint4(0u,0u,0u,0u);

        float c0 = 0.f, c1 = 0.f, c2 = 0.f, c3 = 0.f;
        unsigned mw[4] = {mk.x, mk.y, mk.z, mk.w};
        #pragma unroll
        for (int kw = 0; kw < 4; ++kw) {
            unsigned m = mw[kw];
            while (m) {
                int j = __ffs(m) - 1;
                m &= m - 1;
                float4 v = *reinterpret_cast<const float4*>(
                    &w2s[(kw * 32 + j) * H_DIM + lane * 4]);
                c0 = __fadd_rn(c0, v.x);
                c1 = __fadd_rn(c1, v.y);
                c2 = __fadd_rn(c2, v.z);
                c3 = __fadd_rn(c3, v.w);
            }
        }
        float4 o;
        o.x = __fadd_rn(c0, b2j[0]);
        o.y = __fadd_rn(c1, b2j[1]);
        o.z = __fadd_rn(c2, b2j[2]);
        o.w = __fadd_rn(c3, b2j[3]);
        reinterpret_cast<float4*>(g_cur2)[(base + tt) * 32 + lane] = o;
        mk = nk;
    }
}

// ---------------- lif2: 65536 scalar scans -> masks2 ----------------
// warp = (b, w); lane handles p = w*32+lane, true h2 = (p>>2)+32*(p&3)
__global__ __launch_bounds__(256, 4)
void lif2_kernel(const float* __restrict__ hidden, const float* __restrict__ beta2)
{
    const int lane = threadIdx.x & 31;
    const int wg   = blockIdx.x * 8 + (threadIdx.x >> 5);
    const int b    = wg >> 2, w = wg & 3;
    const int p    = w * 32 + lane;
    const int h2   = (p >> 2) + 32 * (p & 3);

    const float beta = fminf(fmaxf(beta2[h2], 0.0f), 1.0f);
    float mem = hidden[(size_t)b * 2 * H_DIM + H_DIM + h2];
    const float* cb = g_cur2 + (size_t)b * T_STEPS * H_DIM + p;
    unsigned* mout = reinterpret_cast<unsigned*>(g_m2) + (size_t)b * T_STEPS * 4 + w;

    float cur[8], nxt[8];
    #pragma unroll
    for (int i = 0; i < 8; ++i) cur[i] = cb[(size_t)i * H_DIM];

    for (int t0 = 0; t0 < T_STEPS; t0 += 8) {
        if (t0 + 8 < T_STEPS) {
            #pragma unroll
            for (int i = 0; i < 8; ++i) nxt[i] = cb[(size_t)(t0 + 8 + i) * H_DIM];
        }
        #pragma unroll
        for (int u = 0; u < 8; ++u) {
            float reset = (mem > 1.0f) ? 1.0f : 0.0f;
            float m = __fsub_rn(__fadd_rn(__fmul_rn(beta, mem), cur[u]), reset);
            mem = m;
            unsigned msk = __ballot_sync(0xFFFFFFFFu, m > 1.0f);
            if (lane == 0) mout[(size_t)(t0 + u) * 4] = msk;
        }
        #pragma unroll
        for (int i = 0; i < 8; ++i) cur[i] = nxt[i];
    }
}

// ---------------- outk: layer-3 sparse gather, 2 tasks per warp ----------------
__global__ __launch_bounds__(256, 4)
void out_kernel(const float* __restrict__ b3, float* __restrict__ out)
{
    __shared__ float w3s[H_DIM * A_DIM];
    const int tid = threadIdx.x;
    for (int i = tid; i < H_DIM * A_DIM; i += 256) w3s[i] = g_W3p[i];
    __syncthreads();

    const int lane = tid & 31;
    const int a    = lane & 15;
    const float b3a = b3[a];

    const int W    = blockIdx.x * 8 + (tid >> 5);
    const size_t task = (size_t)2 * W + (lane >> 4);   // (b,t) flat index

    uint4 mk = g_m2[task];
    float o = 0.f;
    unsigned mw[4] = {mk.x, mk.y, mk.z, mk.w};
    #pragma unroll
    for (int w = 0; w < 4; ++w) {
        unsigned m = mw[w];
        while (m) {
            int j = __ffs(m) - 1;
            m &= m - 1;
            o = __fadd_rn(o, w3s[(w * 32 + j) * A_DIM + a]);
        }
    }
    o = __fadd_rn(o, b3a);
    out[task * A_DIM + a] = o;
}

extern "C" void kernel_launch(void* const* d_in, const int* in_sizes, int n_in,
                              void* d_out, int out_size) {
    const float* state  = (const float*)d_in[0];  // [512,1024,128]
    const float* hidden = (const float*)d_in[1];  // [512,1,2,128]
    const float* W1     = (const float*)d_in[2];
    const float* b1     = (const float*)d_in[3];
    const float* beta1  = (const float*)d_in[4];
    const float* W2     = (const float*)d_in[5];
    const float* b2     = (const float*)d_in[6];
    const float* beta2  = (const float*)d_in[7];
    const float* W3     = (const float*)d_in[8];
    const float* b3     = (const float*)d_in[9];
    float* out = (float*)d_out;                   // [512,1024,16]

    cudaFuncSetAttribute(gemm_kernel,
                         cudaFuncAttributeMaxDynamicSharedMemorySize, GEMM_SMEM);
    cudaFuncSetAttribute(cur2_kernel,
                         cudaFuncAttributeMaxDynamicSharedMemorySize, C2_SMEM);

    prep_kernel<<<64, 256>>>(W1, W2, W3);
    gemm_kernel<<<M_TOT / GM_M, GM_THR, GEMM_SMEM>>>(state, b1);
    lif1_kernel<<<256, 256>>>(hidden, beta1);
    cur2_kernel<<<4096, 256, C2_SMEM>>>(b2);
    lif2_kernel<<<256, 256>>>(hidden, beta2);
    out_kernel<<<32768, 256>>>(b3, out);
}

// round 8
// speedup vs baseline: 2.4464x; 1.0268x over previous
#include <cuda_runtime.h>
#include <cstdint>

// DSQN forward: B=512, T=1024, F=128, H=128, A=16. Faithful fp32.
//
// Numerics contract (verified rel_err 5.5e-9):
//   cur1 = sequential-k FMA dot (acc 0) THEN + b1      [GEMM, f32x2 exact]
//   mem  = ((clip(beta)*mem) + cur) - reset            (3 separate roundings)
//   cur2 = ascending-h1 sum of W2^T cols THEN + b2     (bitwise = dense seq-k)
//   out  = sum of W3 cols THEN + b3  (order permuted: output-only rounding)
//
// R8: GEMM rework (was LDS-wavefront-bound at ~400us, floor 252us):
//   - x loaded via conflict-free LDS.128 every 4 k (stride 132: phase banks
//     4i..4i+3 tile 0..31 -> zero conflicts)
//   - 2m x 32n per warp: 128 FFMA2 per 4k vs 40 LDS wavefronts -> fma-bound
//   - 128-thr blocks, 2 blocks/SM (2x97KB smem), 8 warps/SM
// lif1/cur2/lif2/out unchanged (cur2 at smem-crossbar floor ~100us).

#define T_STEPS 1024
#define F_DIM   128
#define H_DIM   128
#define A_DIM   16
#define B_TOT   512
#define M_TOT   (B_TOT * T_STEPS)      // 524288

__device__ float g_cur1[M_TOT * H_DIM];            // 268 MB
__device__ float g_cur2[M_TOT * H_DIM];            // 268 MB (permuted h2: p)
__device__ float g_W1T[F_DIM * H_DIM];             // [k][n]
__device__ float g_W2p[H_DIM * H_DIM];             // [h1][(h2&31)*4+(h2>>5)]
__device__ float g_W3p[H_DIM * A_DIM];             // [p][a], h2(p)=(p>>2)+32*(p&3)
__device__ uint4 g_m1[M_TOT];                      // spk1 masks per (b,t)
__device__ uint4 g_m2[M_TOT];                      // spk2 masks per (b,t)

// ---------------- prep: weight layouts ----------------
__global__ void prep_kernel(const float* __restrict__ W1,
                            const float* __restrict__ W2,
                            const float* __restrict__ W3)
{
    int i = threadIdx.x + blockIdx.x * blockDim.x;
    if (i < H_DIM * F_DIM) {
        int n = i >> 7, k = i & 127;
        g_W1T[k * H_DIM + n] = W1[i];                 // W1T[k][n]
        int h2 = n, h1 = k;                           // i = h2*128 + h1
        g_W2p[h1 * H_DIM + (h2 & 31) * 4 + (h2 >> 5)] = W2[i];
    }
    if (i < H_DIM * A_DIM) {
        int p = i >> 4, a = i & 15;
        int h2 = (p >> 2) + 32 * (p & 3);
        g_W3p[p * A_DIM + a] = W3[a * H_DIM + h2];
    }
}

// ---------------- gemm: cur1 = X @ W1^T + b1 (fma.rn.f32x2) ----------------
#define GM_M      64
#define GM_THR    128
#define XS_STRIDE 132
#define GEMM_SMEM ((F_DIM * H_DIM + GM_M * XS_STRIDE) * 4)   // 97.3 KB

__global__ __launch_bounds__(GM_THR, 2)
void gemm_kernel(const float* __restrict__ state, const float* __restrict__ b1)
{
    extern __shared__ float sg[];
    float* w1t_s = sg;                          // [k][n] 128x128
    float* x_s   = sg + F_DIM * H_DIM;          // [m][k] 64x132

    const int tid  = threadIdx.x;
    const int lane = tid & 31;
    const int wrp  = tid >> 5;                  // 0..3
    const int m0   = blockIdx.x * GM_M;
    const int n0   = wrp * 32;

    // load W1T (coalesced, conflict-free)
    #pragma unroll 8
    for (int i = tid; i < (F_DIM * H_DIM) / 4; i += GM_THR)
        reinterpret_cast<float4*>(w1t_s)[i] =
            reinterpret_cast<const float4*>(g_W1T)[i];
    // load X tile (coalesced LDG.128; STS.128 conflict-free: banks 4*k4 tile phases)
    #pragma unroll 4
    for (int i = tid; i < GM_M * 32; i += GM_THR) {
        int m = i >> 5, k4 = i & 31;
        float4 v = reinterpret_cast<const float4*>(state)[(size_t)(m0 + m) * 32 + k4];
        *reinterpret_cast<float4*>(&x_s[m * XS_STRIDE + 4 * k4]) = v;
    }
    __syncthreads();

    // acc: A0/A1 for m = lane / lane+32, 16 n-pairs each (n = n0+2p, n0+2p+1)
    unsigned long long A0[16], A1[16];
    #pragma unroll
    for (int p = 0; p < 16; ++p) { A0[p] = 0ull; A1[p] = 0ull; }

    const float* xr0 = &x_s[lane * XS_STRIDE];
    const float* xr1 = &x_s[(lane + 32) * XS_STRIDE];

    #pragma unroll 2
    for (int k = 0; k < F_DIM; k += 4) {
        // conflict-free LDS.128 (stride 132 words: phase banks 4i..4i+3 tile 0..31)
        float4 xa = *reinterpret_cast<const float4*>(&xr0[k]);
        float4 xb = *reinterpret_cast<const float4*>(&xr1[k]);
        float xav[4] = {xa.x, xa.y, xa.z, xa.w};
        float xbv[4] = {xb.x, xb.y, xb.z, xb.w};
        #pragma unroll
        for (int j = 0; j < 4; ++j) {
            unsigned long long px0, px1;
            asm("mov.b64 %0, {%1, %1};" : "=l"(px0) : "f"(xav[j]));
            asm("mov.b64 %0, {%1, %1};" : "=l"(px1) : "f"(xbv[j]));
            const ulonglong2* wp =
                reinterpret_cast<const ulonglong2*>(&w1t_s[(k + j) * H_DIM + n0]);
            #pragma unroll
            for (int q = 0; q < 8; ++q) {
                ulonglong2 w2 = wp[q];              // broadcast LDS.128
                asm("fma.rn.f32x2 %0, %1, %2, %0;" : "+l"(A0[2*q  ]) : "l"(px0), "l"(w2.x));
                asm("fma.rn.f32x2 %0, %1, %2, %0;" : "+l"(A0[2*q+1]) : "l"(px0), "l"(w2.y));
                asm("fma.rn.f32x2 %0, %1, %2, %0;" : "+l"(A1[2*q  ]) : "l"(px1), "l"(w2.x));
                asm("fma.rn.f32x2 %0, %1, %2, %0;" : "+l"(A1[2*q+1]) : "l"(px1), "l"(w2.y));
            }
        }
    }

    // epilogue: + b1 (separate rounding, after full dot), store 32 n per m
    float bn[32];
    #pragma unroll
    for (int j = 0; j < 32; ++j) bn[j] = b1[n0 + j];

    #pragma unroll
    for (int mi = 0; mi < 2; ++mi) {
        const unsigned long long* ap = mi ? A1 : A0;
        size_t mg = (size_t)(m0 + lane + 32 * mi);
        #pragma unroll
        for (int q2 = 0; q2 < 8; ++q2) {
            float f0, f1, f2, f3;
            asm("mov.b64 {%0, %1}, %2;" : "=f"(f0), "=f"(f1) : "l"(ap[2*q2]));
            asm("mov.b64 {%0, %1}, %2;" : "=f"(f2), "=f"(f3) : "l"(ap[2*q2+1]));
            float4 o;
            o.x = __fadd_rn(f0, bn[4*q2+0]);
            o.y = __fadd_rn(f1, bn[4*q2+1]);
            o.z = __fadd_rn(f2, bn[4*q2+2]);
            o.w = __fadd_rn(f3, bn[4*q2+3]);
            reinterpret_cast<float4*>(g_cur1)[mg * 32 + (n0 >> 2) + q2] = o;
        }
    }
}

// ---------------- lif1: 65536 scalar scans -> masks1 ----------------
__global__ __launch_bounds__(256, 4)
void lif1_kernel(const float* __restrict__ hidden, const float* __restrict__ beta1)
{
    const int lane = threadIdx.x & 31;
    const int wg   = blockIdx.x * 8 + (threadIdx.x >> 5);
    const int b    = wg >> 2, g = wg & 3;
    const int h    = g * 32 + lane;

    const float beta = fminf(fmaxf(beta1[h], 0.0f), 1.0f);
    float mem = hidden[(size_t)b * 2 * H_DIM + h];
    const float* cb = g_cur1 + (size_t)b * T_STEPS * H_DIM + h;
    unsigned* mout = reinterpret_cast<unsigned*>(g_m1) + (size_t)b * T_STEPS * 4 + g;

    float cur[8], nxt[8];
    #pragma unroll
    for (int i = 0; i < 8; ++i) cur[i] = cb[(size_t)i * H_DIM];

    for (int t0 = 0; t0 < T_STEPS; t0 += 8) {
        if (t0 + 8 < T_STEPS) {
            #pragma unroll
            for (int i = 0; i < 8; ++i) nxt[i] = cb[(size_t)(t0 + 8 + i) * H_DIM];
        }
        #pragma unroll
        for (int u = 0; u < 8; ++u) {
            float reset = (mem > 1.0f) ? 1.0f : 0.0f;
            float m = __fsub_rn(__fadd_rn(__fmul_rn(beta, mem), cur[u]), reset);
            mem = m;
            unsigned msk = __ballot_sync(0xFFFFFFFFu, m > 1.0f);
            if (lane == 0) mout[(size_t)(t0 + u) * 4] = msk;
        }
        #pragma unroll
        for (int i = 0; i < 8; ++i) cur[i] = nxt[i];
    }
}

// ---------------- cur2: sparse gather per (b,t), full chip ----------------
#define C2_SMEM (H_DIM * H_DIM * 4)   // 64 KB W2p table

__global__ __launch_bounds__(256, 3)
void cur2_kernel(const float* __restrict__ b2)
{
    extern __shared__ float w2s[];
    const int tid  = threadIdx.x;
    const int lane = tid & 31;

    #pragma unroll 4
    for (int i = tid; i < (H_DIM * H_DIM) / 4; i += 256)
        reinterpret_cast<float4*>(w2s)[i] =
            reinterpret_cast<const float4*>(g_W2p)[i];

    float b2j[4];
    #pragma unroll
    for (int j = 0; j < 4; ++j) b2j[j] = b2[lane + 32 * j];
    __syncthreads();

    const int W  = blockIdx.x * 8 + (tid >> 5);
    const int b  = W >> 6;
    const int t0 = (W & 63) * 16;
    const size_t base = (size_t)b * T_STEPS + t0;

    uint4 mk = g_m1[base];
    #pragma unroll 2
    for (int tt = 0; tt < 16; ++tt) {
        uint4 nk = (tt + 1 < 16) ? g_m1[base + tt + 1] : make_uint4(0u,0u,0u,0u);

        float c0 = 0.f, c1 = 0.f, c2 = 0.f, c3 = 0.f;
        unsigned mw[4] = {mk.x, mk.y, mk.z, mk.w};
        #pragma unroll
        for (int kw = 0; kw < 4; ++kw) {
            unsigned m = mw[kw];
            while (m) {
                int j = __ffs(m) - 1;
                m &= m - 1;
                float4 v = *reinterpret_cast<const float4*>(
                    &w2s[(kw * 32 + j) * H_DIM + lane * 4]);
                c0 = __fadd_rn(c0, v.x);
                c1 = __fadd_rn(c1, v.y);
                c2 = __fadd_rn(c2, v.z);
                c3 = __fadd_rn(c3, v.w);
            }
        }
        float4 o;
        o.x = __fadd_rn(c0, b2j[0]);
        o.y = __fadd_rn(c1, b2j[1]);
        o.z = __fadd_rn(c2, b2j[2]);
        o.w = __fadd_rn(c3, b2j[3]);
        reinterpret_cast<float4*>(g_cur2)[(base + tt) * 32 + lane] = o;
        mk = nk;
    }
}

// ---------------- lif2: 65536 scalar scans -> masks2 ----------------
__global__ __launch_bounds__(256, 4)
void lif2_kernel(const float* __restrict__ hidden, const float* __restrict__ beta2)
{
    const int lane = threadIdx.x & 31;
    const int wg   = blockIdx.x * 8 + (threadIdx.x >> 5);
    const int b    = wg >> 2, w = wg & 3;
    const int p    = w * 32 + lane;
    const int h2   = (p >> 2) + 32 * (p & 3);

    const float beta = fminf(fmaxf(beta2[h2], 0.0f), 1.0f);
    float mem = hidden[(size_t)b * 2 * H_DIM + H_DIM + h2];
    const float* cb = g_cur2 + (size_t)b * T_STEPS * H_DIM + p;
    unsigned* mout = reinterpret_cast<unsigned*>(g_m2) + (size_t)b * T_STEPS * 4 + w;

    float cur[8], nxt[8];
    #pragma unroll
    for (int i = 0; i < 8; ++i) cur[i] = cb[(size_t)i * H_DIM];

    for (int t0 = 0; t0 < T_STEPS; t0 += 8) {
        if (t0 + 8 < T_STEPS) {
            #pragma unroll
            for (int i = 0; i < 8; ++i) nxt[i] = cb[(size_t)(t0 + 8 + i) * H_DIM];
        }
        #pragma unroll
        for (int u = 0; u < 8; ++u) {
            float reset = (mem > 1.0f) ? 1.0f : 0.0f;
            float m = __fsub_rn(__fadd_rn(__fmul_rn(beta, mem), cur[u]), reset);
            mem = m;
            unsigned msk = __ballot_sync(0xFFFFFFFFu, m > 1.0f);
            if (lane == 0) mout[(size_t)(t0 + u) * 4] = msk;
        }
        #pragma unroll
        for (int i = 0; i < 8; ++i) cur[i] = nxt[i];
    }
}

// ---------------- outk: layer-3 sparse gather, 2 tasks per warp ----------------
__global__ __launch_bounds__(256, 4)
void out_kernel(const float* __restrict__ b3, float* __restrict__ out)
{
    __shared__ float w3s[H_DIM * A_DIM];
    const int tid = threadIdx.x;
    for (int i = tid; i < H_DIM * A_DIM; i += 256) w3s[i] = g_W3p[i];
    __syncthreads();

    const int lane = tid & 31;
    const int a    = lane & 15;
    const float b3a = b3[a];

    const int W    = blockIdx.x * 8 + (tid >> 5);
    const size_t task = (size_t)2 * W + (lane >> 4);   // (b,t) flat index

    uint4 mk = g_m2[task];
    float o = 0.f;
    unsigned mw[4] = {mk.x, mk.y, mk.z, mk.w};
    #pragma unroll
    for (int w = 0; w < 4; ++w) {
        unsigned m = mw[w];
        while (m) {
            int j = __ffs(m) - 1;
            m &= m - 1;
            o = __fadd_rn(o, w3s[(w * 32 + j) * A_DIM + a]);
        }
    }
    o = __fadd_rn(o, b3a);
    out[task * A_DIM + a] = o;
}

extern "C" void kernel_launch(void* const* d_in, const int* in_sizes, int n_in,
                              void* d_out, int out_size) {
    const float* state  = (const float*)d_in[0];  // [512,1024,128]
    const float* hidden = (const float*)d_in[1];  // [512,1,2,128]
    const float* W1     = (const float*)d_in[2];
    const float* b1     = (const float*)d_in[3];
    const float* beta1  = (const float*)d_in[4];
    const float* W2     = (const float*)d_in[5];
    const float* b2     = (const float*)d_in[6];
    const float* beta2  = (const float*)d_in[7];
    const float* W3     = (const float*)d_in[8];
    const float* b3     = (const float*)d_in[9];
    float* out = (float*)d_out;                   // [512,1024,16]

    cudaFuncSetAttribute(gemm_kernel,
                         cudaFuncAttributeMaxDynamicSharedMemorySize, GEMM_SMEM);
    cudaFuncSetAttribute(cur2_kernel,
                         cudaFuncAttributeMaxDynamicSharedMemorySize, C2_SMEM);

    prep_kernel<<<64, 256>>>(W1, W2, W3);
    gemm_kernel<<<M_TOT / GM_M, GM_THR, GEMM_SMEM>>>(state, b1);
    lif1_kernel<<<256, 256>>>(hidden, beta1);
    cur2_kernel<<<4096, 256, C2_SMEM>>>(b2);
    lif2_kernel<<<256, 256>>>(hidden, beta2);
    out_kernel<<<32768, 256>>>(b3, out);
}